// round 7
// baseline (speedup 1.0000x reference)
#include <cuda_runtime.h>

#define NB 256
#define NP 20000

// scratch: 256 batches x 45 packed upper-triangular entries of XwX
__device__ float g_M[NB * 45];

__device__ __host__ __forceinline__ constexpr int tidx(int i, int j) {
    return 9 * i - i * (i - 1) / 2 + (j - i);
}

// ---------------------------------------------------------------------------
// Kernel 1: per-batch weighted Gram matrix. BITWISE-identical accumulation to
// the round-2 passing kernel (same per-thread point sequence t, t+256, ...;
// same fma order per accumulator; same shfl+smem reduction). Manual unroll x2
// only reorders LOADS, never the s[k] fma chains.
// ---------------------------------------------------------------------------
__device__ __forceinline__ void accum_point(float4 p, float wt, float* __restrict__ s) {
    float v[9];
    v[0] = p.z * p.x; v[1] = p.z * p.y; v[2] = p.z;
    v[3] = p.w * p.x; v[4] = p.w * p.y; v[5] = p.w;
    v[6] = p.x;       v[7] = p.y;       v[8] = 1.f;
    float wv[9];
#pragma unroll
    for (int k = 0; k < 9; k++) wv[k] = wt * v[k];
    int idx = 0;
#pragma unroll
    for (int i2 = 0; i2 < 9; i2++) {
#pragma unroll
        for (int j = i2; j < 9; j++) {
            s[idx] = fmaf(v[i2], wv[j], s[idx]);
            idx++;
        }
    }
}

__global__ void __launch_bounds__(256) xtx_kernel(const float4* __restrict__ x,
                                                  const float* __restrict__ w) {
    int b = blockIdx.x;
    const float4* xb = x + (size_t)b * NP;
    const float*  wb = w + (size_t)b * NP;

    float s[45];
#pragma unroll
    for (int k = 0; k < 45; k++) s[k] = 0.f;

    int i = threadIdx.x;
    // pairs: loads hoisted, accumulation strictly in-order (i before i+256)
    for (; i + 256 < NP; i += 512) {
        float4 p0 = xb[i];
        float  w0 = wb[i];
        float4 p1 = xb[i + 256];
        float  w1 = wb[i + 256];
        accum_point(p0, w0, s);
        accum_point(p1, w1, s);
    }
    if (i < NP) {
        float4 p0 = xb[i];
        float  w0 = wb[i];
        accum_point(p0, w0, s);
    }

    // intra-warp reduction (identical to round 2)
#pragma unroll
    for (int k = 0; k < 45; k++) {
#pragma unroll
        for (int o = 16; o > 0; o >>= 1)
            s[k] += __shfl_xor_sync(0xffffffffu, s[k], o);
    }

    __shared__ float sm[8][45];
    int wid = threadIdx.x >> 5, lane = threadIdx.x & 31;
    if (lane == 0) {
#pragma unroll
        for (int k = 0; k < 45; k++) sm[wid][k] = s[k];
    }
    __syncthreads();
    if (threadIdx.x < 45) {
        float t = 0.f;
#pragma unroll
        for (int q = 0; q < 8; q++) t += sm[q][threadIdx.x];
        g_M[b * 45 + threadIdx.x] = t;
    }
}

// ---------------------------------------------------------------------------
// LAPACK fp32 helpers (identical to round-2 passing kernel)
// ---------------------------------------------------------------------------
#define LEPS    5.9604645e-8f
#define LEPS2   (LEPS * LEPS)
#define LSAFMIN 1.17549435e-38f

__device__ __forceinline__ float slapy2(float x, float y) {
    float xa = fabsf(x), ya = fabsf(y);
    float w = fmaxf(xa, ya), z = fminf(xa, ya);
    if (z == 0.f) return w;
    float t = z / w;
    return w * sqrtf(1.f + t * t);
}

__device__ __forceinline__ void slartg(float f, float g, float& c, float& s, float& r) {
    if (g == 0.f) { c = 1.f; s = 0.f; r = f; }
    else if (f == 0.f) { c = 0.f; s = (g >= 0.f ? 1.f : -1.f); r = fabsf(g); }
    else {
        float d = sqrtf(f * f + g * g);
        c = fabsf(f) / d;
        r = copysignf(d, f);
        s = g / r;
    }
}

__device__ void slaev2(float a, float b, float c,
                       float& rt1, float& rt2, float& cs1, float& sn1) {
    float sm = a + c, df = a - c, adf = fabsf(df);
    float tb = b + b, ab = fabsf(tb);
    float acmx, acmn;
    if (fabsf(a) > fabsf(c)) { acmx = a; acmn = c; } else { acmx = c; acmn = a; }
    float rt;
    if (adf > ab)      { float t = ab / adf; rt = adf * sqrtf(1.f + t * t); }
    else if (adf < ab) { float t = adf / ab; rt = ab * sqrtf(1.f + t * t); }
    else               { rt = ab * sqrtf(2.f); }
    int sgn1;
    if (sm < 0.f) {
        rt1 = 0.5f * (sm - rt); sgn1 = -1;
        rt2 = (acmx / rt1) * acmn - (b / rt1) * b;
    } else if (sm > 0.f) {
        rt1 = 0.5f * (sm + rt); sgn1 = 1;
        rt2 = (acmx / rt1) * acmn - (b / rt1) * b;
    } else {
        rt1 = 0.5f * rt; rt2 = -0.5f * rt; sgn1 = 1;
    }
    float cs; int sgn2;
    if (df >= 0.f) { cs = df + rt; sgn2 = 1; } else { cs = df - rt; sgn2 = -1; }
    float acs = fabsf(cs);
    if (acs > ab) {
        float ct = -tb / cs;
        sn1 = 1.f / sqrtf(1.f + ct * ct);
        cs1 = ct * sn1;
    } else {
        if (ab == 0.f) { cs1 = 1.f; sn1 = 0.f; }
        else {
            float tn = -cs / tb;
            cs1 = 1.f / sqrtf(1.f + tn * tn);
            sn1 = tn * cs1;
        }
    }
    if (sgn1 == sgn2) { float tn = cs1; cs1 = -sn1; sn1 = tn; }
}

// ---------------------------------------------------------------------------
// Kernel 2: LAPACK ssyevd replica. Scalar path (ssytd2 + ssteqr dd/e/branches)
// is source-identical to round 2; the Z matrix is replaced by a rotation log
// (stored in SHARED memory -- one thread per CTA, ~22.4 KB smem) replayed in
// reverse onto e_kmin (same matrix product, different parenthesization only
// -> cannot change any branch/sign).
// ---------------------------------------------------------------------------
#define MAXROT 2240

__global__ void eig_kernel(float* __restrict__ out) {
    int b = blockIdx.x;

    // rotation log in shared memory (single thread per CTA -> no conflicts,
    // no per-thread local-memory growth)
    __shared__ short jr[MAXROT];
    __shared__ float cr[MAXROT];
    __shared__ float sr[MAXROT];

    float A[9][9];
#pragma unroll
    for (int i = 0; i < 9; i++)
#pragma unroll
        for (int j = i; j < 9; j++) {
            float v = g_M[b * 45 + tidx(i, j)];
            A[i][j] = v; A[j][i] = v;
        }

    float dd[9], e[8], tau[8];

    // ---- ssytd2 (lower), identical to round 2 ----
    for (int i = 0; i < 8; i++) {
        float alpha = A[i + 1][i];
        float xn2 = 0.f;
        for (int k = i + 2; k < 9; k++) xn2 += A[k][i] * A[k][i];
        float taui;
        if (xn2 == 0.f) {
            taui = 0.f;
            e[i] = alpha;
        } else {
            float xnorm = sqrtf(xn2);
            float beta = -copysignf(slapy2(alpha, xnorm), alpha);
            taui = (beta - alpha) / beta;
            float invd = 1.f / (alpha - beta);
            for (int k = i + 2; k < 9; k++) A[k][i] *= invd;
            e[i] = beta;
        }
        if (taui != 0.f) {
            float v[9], wv[9];
            v[i + 1] = 1.f;
            for (int k = i + 2; k < 9; k++) v[k] = A[k][i];
            for (int r = i + 1; r < 9; r++) {
                float acc = 0.f;
                for (int c = i + 1; c < 9; c++) acc += A[r][c] * v[c];
                wv[r] = taui * acc;
            }
            float dxv = 0.f;
            for (int r = i + 1; r < 9; r++) dxv += wv[r] * v[r];
            float al2 = -0.5f * taui * dxv;
            for (int r = i + 1; r < 9; r++) wv[r] += al2 * v[r];
            for (int r = i + 1; r < 9; r++)
                for (int c = i + 1; c < 9; c++)
                    A[r][c] -= v[r] * wv[c] + wv[r] * v[c];
        }
        dd[i] = A[i][i];
        tau[i] = taui;
    }
    dd[8] = A[8][8];

    // ---- ssteqr (compz='I'), scalar path identical; Z ops recorded ----
    int nrot = 0;

    const int NMAXIT = 9 * 30;
    int jtot = 0;
    int l1 = 0;
    while (l1 < 9) {
        if (l1 > 0) e[l1 - 1] = 0.f;
        int m;
        for (m = l1; m < 8; m++) {
            float tst = fabsf(e[m]);
            if (tst == 0.f) break;
            if (tst <= (sqrtf(fabsf(dd[m])) * sqrtf(fabsf(dd[m + 1]))) * LEPS) {
                e[m] = 0.f;
                break;
            }
        }
        int l = l1, lend = m;
        l1 = m + 1;
        if (lend == l) continue;
        if (fabsf(dd[lend]) < fabsf(dd[l])) { int t = l; l = lend; lend = t; }

        if (lend > l) {
            // ---- QL ----
            for (;;) {
                int mm;
                for (mm = l; mm < lend; mm++) {
                    float tst = e[mm] * e[mm];
                    if (tst <= (LEPS2 * fabsf(dd[mm])) * fabsf(dd[mm + 1]) + LSAFMIN) break;
                }
                if (mm < lend) e[mm] = 0.f;
                float p = dd[l];
                if (mm == l) {
                    dd[l] = p;
                    l++;
                    if (l <= lend) continue;
                    break;
                }
                if (mm == l + 1) {
                    float rt1, rt2, c2, s2;
                    slaev2(dd[l], e[l], dd[l + 1], rt1, rt2, c2, s2);
                    if (nrot < MAXROT) { jr[nrot] = (short)l; cr[nrot] = c2; sr[nrot] = s2; nrot++; }
                    dd[l] = rt1; dd[l + 1] = rt2; e[l] = 0.f;
                    l += 2;
                    if (l <= lend) continue;
                    break;
                }
                if (jtot >= NMAXIT) break;
                jtot++;
                float g = (dd[l + 1] - p) / (2.f * e[l]);
                float r2 = slapy2(g, 1.f);
                g = dd[mm] - p + e[l] / (g + copysignf(r2, g));
                float s1 = 1.f, c1 = 1.f;
                p = 0.f;
                for (int i = mm - 1; i >= l; i--) {
                    float f = s1 * e[i];
                    float bb = c1 * e[i];
                    slartg(g, f, c1, s1, r2);
                    if (i != mm - 1) e[i + 1] = r2;
                    g = dd[i + 1] - p;
                    r2 = (dd[i] - g) * s1 + 2.f * c1 * bb;
                    p = s1 * r2;
                    dd[i + 1] = g + p;
                    g = c1 * r2 - bb;
                    if (nrot < MAXROT) { jr[nrot] = (short)i; cr[nrot] = c1; sr[nrot] = -s1; nrot++; }
                }
                dd[l] = dd[l] - p;
                e[l] = g;
            }
        } else {
            // ---- QR ----
            for (;;) {
                int mm;
                for (mm = l; mm > lend; mm--) {
                    float tst = e[mm - 1] * e[mm - 1];
                    if (tst <= (LEPS2 * fabsf(dd[mm])) * fabsf(dd[mm - 1]) + LSAFMIN) break;
                }
                if (mm > lend) e[mm - 1] = 0.f;
                float p = dd[l];
                if (mm == l) {
                    dd[l] = p;
                    l--;
                    if (l >= lend) continue;
                    break;
                }
                if (mm == l - 1) {
                    float rt1, rt2, c2, s2;
                    slaev2(dd[l - 1], e[l - 1], dd[l], rt1, rt2, c2, s2);
                    if (nrot < MAXROT) { jr[nrot] = (short)(l - 1); cr[nrot] = c2; sr[nrot] = s2; nrot++; }
                    dd[l - 1] = rt1; dd[l] = rt2; e[l - 1] = 0.f;
                    l -= 2;
                    if (l >= lend) continue;
                    break;
                }
                if (jtot >= NMAXIT) break;
                jtot++;
                float g = (dd[l - 1] - p) / (2.f * e[l - 1]);
                float r2 = slapy2(g, 1.f);
                g = dd[mm] - p + e[l - 1] / (g + copysignf(r2, g));
                float s1 = 1.f, c1 = 1.f;
                p = 0.f;
                for (int i = mm; i <= l - 1; i++) {
                    float f = s1 * e[i];
                    float bb = c1 * e[i];
                    slartg(g, f, c1, s1, r2);
                    if (i != mm) e[i - 1] = r2;
                    g = dd[i] - p;
                    r2 = (dd[i + 1] - g) * s1 + 2.f * c1 * bb;
                    p = s1 * r2;
                    dd[i] = g + p;
                    g = c1 * r2 - bb;
                    if (nrot < MAXROT) { jr[nrot] = (short)i; cr[nrot] = c1; sr[nrot] = s1; nrot++; }
                }
                dd[l] = dd[l] - p;
                e[l - 1] = g;
            }
        }
    }

    // ---- first index achieving the min eigenvalue (== round-2 sort col 0) ----
    int kmin = 0;
    float p0 = dd[0];
    for (int j = 1; j < 9; j++)
        if (dd[j] < p0) { p0 = dd[j]; kmin = j; }

    // ---- replay rotations in reverse onto e_kmin:  z = G_1 (G_2 ... (G_T e_kmin)) ----
    float z[9];
#pragma unroll
    for (int r = 0; r < 9; r++) z[r] = (r == kmin) ? 1.f : 0.f;
    for (int t = nrot - 1; t >= 0; t--) {
        int j = jr[t];
        float c = cr[t], s = sr[t];
        float vj = z[j], vj1 = z[j + 1];
        z[j]     = c * vj - s * vj1;
        z[j + 1] = s * vj + c * vj1;
    }

    // ---- back-transform: z <- H(1)...H(8) z (identical to round 2) ----
    for (int i = 7; i >= 0; i--) {
        if (tau[i] == 0.f) continue;
        float dot = z[i + 1];
        for (int k = i + 2; k < 9; k++) dot += A[k][i] * z[k];
        float tdot = tau[i] * dot;
        z[i + 1] -= tdot;
        for (int k = i + 2; k < 9; k++) z[k] -= tdot * A[k][i];
    }

    // ---- normalize ----
    float nrm = 0.f;
    for (int k = 0; k < 9; k++) nrm += z[k] * z[k];
    float inv = 1.f / sqrtf(nrm);
    for (int k = 0; k < 9; k++) out[b * 9 + k] = z[k] * inv;
}

extern "C" void kernel_launch(void* const* d_in, const int* in_sizes, int n_in,
                              void* d_out, int out_size) {
    const float4* x = (const float4*)d_in[0];  // x_in  (256,1,20000,4) f32
    const float*  w = (const float*)d_in[1];   // weights (256,20000)   f32
    float* out = (float*)d_out;                // (256,9) f32

    xtx_kernel<<<NB, 256>>>(x, w);
    eig_kernel<<<NB, 1>>>(out);
}

// round 8
// speedup vs baseline: 1.1446x; 1.1446x over previous
#include <cuda_runtime.h>

#define NB 256
#define NP 20000

// scratch: 256 batches x 45 packed upper-triangular entries of XwX
__device__ float g_M[NB * 45];

__device__ __host__ __forceinline__ constexpr int tidx(int i, int j) {
    return 9 * i - i * (i - 1) / 2 + (j - i);
}

// ---------------------------------------------------------------------------
// Kernel 1: per-batch weighted Gram matrix. BITWISE-identical accumulation to
// the round-2 passing kernel (same per-thread point sequence t, t+256, ...;
// same fma order per accumulator; same shfl+smem reduction). Manual unroll x4
// only reorders LOADS (MLP=8/thread), never the s[k] fma chains.
// ---------------------------------------------------------------------------
__device__ __forceinline__ void accum_point(float4 p, float wt, float* __restrict__ s) {
    float v[9];
    v[0] = p.z * p.x; v[1] = p.z * p.y; v[2] = p.z;
    v[3] = p.w * p.x; v[4] = p.w * p.y; v[5] = p.w;
    v[6] = p.x;       v[7] = p.y;       v[8] = 1.f;
    float wv[9];
#pragma unroll
    for (int k = 0; k < 9; k++) wv[k] = wt * v[k];
    int idx = 0;
#pragma unroll
    for (int i2 = 0; i2 < 9; i2++) {
#pragma unroll
        for (int j = i2; j < 9; j++) {
            s[idx] = fmaf(v[i2], wv[j], s[idx]);
            idx++;
        }
    }
}

__global__ void __launch_bounds__(256) xtx_kernel(const float4* __restrict__ x,
                                                  const float* __restrict__ w) {
    int b = blockIdx.x;
    const float4* xb = x + (size_t)b * NP;
    const float*  wb = w + (size_t)b * NP;

    float s[45];
#pragma unroll
    for (int k = 0; k < 45; k++) s[k] = 0.f;

    int i = threadIdx.x;
    // quads: loads hoisted (8 loads in flight), accumulation strictly in order
    // i, i+256, i+512, i+768 -- identical chain per s[k] as round 2.
    for (; i + 768 < NP; i += 1024) {
        float4 p0 = xb[i];
        float  w0 = wb[i];
        float4 p1 = xb[i + 256];
        float  w1 = wb[i + 256];
        float4 p2 = xb[i + 512];
        float  w2 = wb[i + 512];
        float4 p3 = xb[i + 768];
        float  w3 = wb[i + 768];
        accum_point(p0, w0, s);
        accum_point(p1, w1, s);
        accum_point(p2, w2, s);
        accum_point(p3, w3, s);
    }
    for (; i < NP; i += 256) {
        float4 p0 = xb[i];
        float  w0 = wb[i];
        accum_point(p0, w0, s);
    }

    // intra-warp reduction (identical to round 2)
#pragma unroll
    for (int k = 0; k < 45; k++) {
#pragma unroll
        for (int o = 16; o > 0; o >>= 1)
            s[k] += __shfl_xor_sync(0xffffffffu, s[k], o);
    }

    __shared__ float sm[8][45];
    int wid = threadIdx.x >> 5, lane = threadIdx.x & 31;
    if (lane == 0) {
#pragma unroll
        for (int k = 0; k < 45; k++) sm[wid][k] = s[k];
    }
    __syncthreads();
    if (threadIdx.x < 45) {
        float t = 0.f;
#pragma unroll
        for (int q = 0; q < 8; q++) t += sm[q][threadIdx.x];
        g_M[b * 45 + threadIdx.x] = t;
    }
}

// ---------------------------------------------------------------------------
// LAPACK fp32 helpers (identical to round-2 passing kernel)
// ---------------------------------------------------------------------------
#define LEPS    5.9604645e-8f
#define LEPS2   (LEPS * LEPS)
#define LSAFMIN 1.17549435e-38f

__device__ __forceinline__ float slapy2(float x, float y) {
    float xa = fabsf(x), ya = fabsf(y);
    float w = fmaxf(xa, ya), z = fminf(xa, ya);
    if (z == 0.f) return w;
    float t = z / w;
    return w * sqrtf(1.f + t * t);
}

__device__ __forceinline__ void slartg(float f, float g, float& c, float& s, float& r) {
    if (g == 0.f) { c = 1.f; s = 0.f; r = f; }
    else if (f == 0.f) { c = 0.f; s = (g >= 0.f ? 1.f : -1.f); r = fabsf(g); }
    else {
        float d = sqrtf(f * f + g * g);
        c = fabsf(f) / d;
        r = copysignf(d, f);
        s = g / r;
    }
}

__device__ void slaev2(float a, float b, float c,
                       float& rt1, float& rt2, float& cs1, float& sn1) {
    float sm = a + c, df = a - c, adf = fabsf(df);
    float tb = b + b, ab = fabsf(tb);
    float acmx, acmn;
    if (fabsf(a) > fabsf(c)) { acmx = a; acmn = c; } else { acmx = c; acmn = a; }
    float rt;
    if (adf > ab)      { float t = ab / adf; rt = adf * sqrtf(1.f + t * t); }
    else if (adf < ab) { float t = adf / ab; rt = ab * sqrtf(1.f + t * t); }
    else               { rt = ab * sqrtf(2.f); }
    int sgn1;
    if (sm < 0.f) {
        rt1 = 0.5f * (sm - rt); sgn1 = -1;
        rt2 = (acmx / rt1) * acmn - (b / rt1) * b;
    } else if (sm > 0.f) {
        rt1 = 0.5f * (sm + rt); sgn1 = 1;
        rt2 = (acmx / rt1) * acmn - (b / rt1) * b;
    } else {
        rt1 = 0.5f * rt; rt2 = -0.5f * rt; sgn1 = 1;
    }
    float cs; int sgn2;
    if (df >= 0.f) { cs = df + rt; sgn2 = 1; } else { cs = df - rt; sgn2 = -1; }
    float acs = fabsf(cs);
    if (acs > ab) {
        float ct = -tb / cs;
        sn1 = 1.f / sqrtf(1.f + ct * ct);
        cs1 = ct * sn1;
    } else {
        if (ab == 0.f) { cs1 = 1.f; sn1 = 0.f; }
        else {
            float tn = -cs / tb;
            cs1 = 1.f / sqrtf(1.f + tn * tn);
            sn1 = tn * cs1;
        }
    }
    if (sgn1 == sgn2) { float tn = cs1; cs1 = -sn1; sn1 = tn; }
}

// ---------------------------------------------------------------------------
// Kernel 2: per-matrix LAPACK ssyevd replica (ssytd2 + ssteqr + backtransform)
// VERBATIM the round-2 passing version (Z maintained inline; ILP-hidden).
// ---------------------------------------------------------------------------
__global__ void eig_kernel(float* __restrict__ out) {
    int b = blockIdx.x;

    float A[9][9];
#pragma unroll
    for (int i = 0; i < 9; i++)
#pragma unroll
        for (int j = i; j < 9; j++) {
            float v = g_M[b * 45 + tidx(i, j)];
            A[i][j] = v; A[j][i] = v;
        }

    float dd[9], e[8], tau[8];

    // ---- ssytd2 (lower) ----
    for (int i = 0; i < 8; i++) {
        float alpha = A[i + 1][i];
        float xn2 = 0.f;
        for (int k = i + 2; k < 9; k++) xn2 += A[k][i] * A[k][i];
        float taui;
        if (xn2 == 0.f) {
            taui = 0.f;
            e[i] = alpha;
        } else {
            float xnorm = sqrtf(xn2);
            float beta = -copysignf(slapy2(alpha, xnorm), alpha);
            taui = (beta - alpha) / beta;
            float invd = 1.f / (alpha - beta);
            for (int k = i + 2; k < 9; k++) A[k][i] *= invd;
            e[i] = beta;
        }
        if (taui != 0.f) {
            float v[9], wv[9];
            v[i + 1] = 1.f;
            for (int k = i + 2; k < 9; k++) v[k] = A[k][i];
            for (int r = i + 1; r < 9; r++) {
                float acc = 0.f;
                for (int c = i + 1; c < 9; c++) acc += A[r][c] * v[c];
                wv[r] = taui * acc;
            }
            float dxv = 0.f;
            for (int r = i + 1; r < 9; r++) dxv += wv[r] * v[r];
            float al2 = -0.5f * taui * dxv;
            for (int r = i + 1; r < 9; r++) wv[r] += al2 * v[r];
            for (int r = i + 1; r < 9; r++)
                for (int c = i + 1; c < 9; c++)
                    A[r][c] -= v[r] * wv[c] + wv[r] * v[c];
        }
        dd[i] = A[i][i];
        tau[i] = taui;
    }
    dd[8] = A[8][8];

    // ---- ssteqr (compz='I') ----
    float Z[9][9];
    for (int r = 0; r < 9; r++)
        for (int c = 0; c < 9; c++) Z[r][c] = (r == c) ? 1.f : 0.f;

    const int NMAXIT = 9 * 30;
    int jtot = 0;
    int l1 = 0;
    while (l1 < 9) {
        if (l1 > 0) e[l1 - 1] = 0.f;
        int m;
        for (m = l1; m < 8; m++) {
            float tst = fabsf(e[m]);
            if (tst == 0.f) break;
            if (tst <= (sqrtf(fabsf(dd[m])) * sqrtf(fabsf(dd[m + 1]))) * LEPS) {
                e[m] = 0.f;
                break;
            }
        }
        int l = l1, lend = m;
        l1 = m + 1;
        if (lend == l) continue;
        if (fabsf(dd[lend]) < fabsf(dd[l])) { int t = l; l = lend; lend = t; }

        if (lend > l) {
            // ---- QL iteration ----
            for (;;) {
                int mm;
                for (mm = l; mm < lend; mm++) {
                    float tst = e[mm] * e[mm];
                    if (tst <= (LEPS2 * fabsf(dd[mm])) * fabsf(dd[mm + 1]) + LSAFMIN) break;
                }
                if (mm < lend) e[mm] = 0.f;
                float p = dd[l];
                if (mm == l) {                       // eigenvalue found
                    dd[l] = p;
                    l++;
                    if (l <= lend) continue;
                    break;
                }
                if (mm == l + 1) {                   // 2x2 block
                    float rt1, rt2, c2, s2;
                    slaev2(dd[l], e[l], dd[l + 1], rt1, rt2, c2, s2);
                    for (int r = 0; r < 9; r++) {
                        float t2 = Z[r][l + 1];
                        Z[r][l + 1] = c2 * t2 - s2 * Z[r][l];
                        Z[r][l]     = s2 * t2 + c2 * Z[r][l];
                    }
                    dd[l] = rt1; dd[l + 1] = rt2; e[l] = 0.f;
                    l += 2;
                    if (l <= lend) continue;
                    break;
                }
                if (jtot >= NMAXIT) break;
                jtot++;
                float g = (dd[l + 1] - p) / (2.f * e[l]);
                float r2 = slapy2(g, 1.f);
                g = dd[mm] - p + e[l] / (g + copysignf(r2, g));
                float s1 = 1.f, c1 = 1.f;
                p = 0.f;
                float cs_[8], sn_[8];
                for (int i = mm - 1; i >= l; i--) {
                    float f = s1 * e[i];
                    float bb = c1 * e[i];
                    slartg(g, f, c1, s1, r2);
                    if (i != mm - 1) e[i + 1] = r2;
                    g = dd[i + 1] - p;
                    r2 = (dd[i] - g) * s1 + 2.f * c1 * bb;
                    p = s1 * r2;
                    dd[i + 1] = g + p;
                    g = c1 * r2 - bb;
                    cs_[i] = c1; sn_[i] = -s1;
                }
                for (int j = mm - 1 - l; j >= 0; j--) {   // slasr 'R','V','B'
                    float cc = cs_[l + j], ss = sn_[l + j];
                    for (int r = 0; r < 9; r++) {
                        float t2 = Z[r][l + j + 1];
                        Z[r][l + j + 1] = cc * t2 - ss * Z[r][l + j];
                        Z[r][l + j]     = ss * t2 + cc * Z[r][l + j];
                    }
                }
                dd[l] = dd[l] - p;
                e[l] = g;
            }
        } else {
            // ---- QR iteration (lend < l) ----
            for (;;) {
                int mm;
                for (mm = l; mm > lend; mm--) {
                    float tst = e[mm - 1] * e[mm - 1];
                    if (tst <= (LEPS2 * fabsf(dd[mm])) * fabsf(dd[mm - 1]) + LSAFMIN) break;
                }
                if (mm > lend) e[mm - 1] = 0.f;
                float p = dd[l];
                if (mm == l) {
                    dd[l] = p;
                    l--;
                    if (l >= lend) continue;
                    break;
                }
                if (mm == l - 1) {
                    float rt1, rt2, c2, s2;
                    slaev2(dd[l - 1], e[l - 1], dd[l], rt1, rt2, c2, s2);
                    for (int r = 0; r < 9; r++) {   // slasr 'F', 2 cols at l-1
                        float t2 = Z[r][l];
                        Z[r][l]     = c2 * t2 - s2 * Z[r][l - 1];
                        Z[r][l - 1] = s2 * t2 + c2 * Z[r][l - 1];
                    }
                    dd[l - 1] = rt1; dd[l] = rt2; e[l - 1] = 0.f;
                    l -= 2;
                    if (l >= lend) continue;
                    break;
                }
                if (jtot >= NMAXIT) break;
                jtot++;
                float g = (dd[l - 1] - p) / (2.f * e[l - 1]);
                float r2 = slapy2(g, 1.f);
                g = dd[mm] - p + e[l - 1] / (g + copysignf(r2, g));
                float s1 = 1.f, c1 = 1.f;
                p = 0.f;
                float cs_[8], sn_[8];
                for (int i = mm; i <= l - 1; i++) {
                    float f = s1 * e[i];
                    float bb = c1 * e[i];
                    slartg(g, f, c1, s1, r2);
                    if (i != mm) e[i - 1] = r2;
                    g = dd[i] - p;
                    r2 = (dd[i + 1] - g) * s1 + 2.f * c1 * bb;
                    p = s1 * r2;
                    dd[i] = g + p;
                    g = c1 * r2 - bb;
                    cs_[i] = c1; sn_[i] = s1;
                }
                for (int j = 0; j <= l - mm - 1; j++) {   // slasr 'R','V','F'
                    float cc = cs_[mm + j], ss = sn_[mm + j];
                    for (int r = 0; r < 9; r++) {
                        float t2 = Z[r][mm + j + 1];
                        Z[r][mm + j + 1] = cc * t2 - ss * Z[r][mm + j];
                        Z[r][mm + j]     = ss * t2 + cc * Z[r][mm + j];
                    }
                }
                dd[l] = dd[l] - p;
                e[l - 1] = g;
            }
        }
    }

    // ---- ssteqr final sort: ascending eigenvalues, swap columns ----
    for (int ii = 1; ii < 9; ii++) {
        int i = ii - 1;
        int k = i;
        float p = dd[i];
        for (int j = ii; j < 9; j++)
            if (dd[j] < p) { k = j; p = dd[j]; }
        if (k != i) {
            dd[k] = dd[i]; dd[i] = p;
            for (int r = 0; r < 9; r++) {
                float t2 = Z[r][i]; Z[r][i] = Z[r][k]; Z[r][k] = t2;
            }
        }
    }

    // ---- back-transform column 0: z <- H(1)...H(8) z ----
    float z[9];
    for (int r = 0; r < 9; r++) z[r] = Z[r][0];
    for (int i = 7; i >= 0; i--) {
        if (tau[i] == 0.f) continue;
        float dot = z[i + 1];
        for (int k = i + 2; k < 9; k++) dot += A[k][i] * z[k];
        float tdot = tau[i] * dot;
        z[i + 1] -= tdot;
        for (int k = i + 2; k < 9; k++) z[k] -= tdot * A[k][i];
    }

    // ---- normalize (reference divides by norm) ----
    float nrm = 0.f;
    for (int k = 0; k < 9; k++) nrm += z[k] * z[k];
    float inv = 1.f / sqrtf(nrm);
    for (int k = 0; k < 9; k++) out[b * 9 + k] = z[k] * inv;
}

extern "C" void kernel_launch(void* const* d_in, const int* in_sizes, int n_in,
                              void* d_out, int out_size) {
    const float4* x = (const float4*)d_in[0];  // x_in  (256,1,20000,4) f32
    const float*  w = (const float*)d_in[1];   // weights (256,20000)   f32
    float* out = (float*)d_out;                // (256,9) f32

    xtx_kernel<<<NB, 256>>>(x, w);
    eig_kernel<<<NB, 1>>>(out);
}

// round 11
// speedup vs baseline: 1.4374x; 1.2558x over previous
#include <cuda_runtime.h>

#define NB 256
#define NP 20000

// scratch: 256 batches x 45 packed upper-triangular entries of XwX
__device__ float g_M[NB * 45];

__device__ __host__ __forceinline__ constexpr int tidx(int i, int j) {
    return 9 * i - i * (i - 1) / 2 + (j - i);
}

// ---------------------------------------------------------------------------
// Kernel 1: per-batch weighted Gram matrix. BITWISE-identical accumulation to
// the round-2 passing kernel (same per-thread point sequence t, t+256, ...;
// same fma order per accumulator; same shfl+smem reduction). Software
// pipelining: the NEXT quad's 8 loads are issued before accumulating the
// current quad -- load order only, never the s[k] fma chains.
// ---------------------------------------------------------------------------
__device__ __forceinline__ void accum_point(float4 p, float wt, float* __restrict__ s) {
    float v[9];
    v[0] = p.z * p.x; v[1] = p.z * p.y; v[2] = p.z;
    v[3] = p.w * p.x; v[4] = p.w * p.y; v[5] = p.w;
    v[6] = p.x;       v[7] = p.y;       v[8] = 1.f;
    float wv[9];
#pragma unroll
    for (int k = 0; k < 9; k++) wv[k] = wt * v[k];
    int idx = 0;
#pragma unroll
    for (int i2 = 0; i2 < 9; i2++) {
#pragma unroll
        for (int j = i2; j < 9; j++) {
            s[idx] = fmaf(v[i2], wv[j], s[idx]);
            idx++;
        }
    }
}

__global__ void __launch_bounds__(256) xtx_kernel(const float4* __restrict__ x,
                                                  const float* __restrict__ w) {
    int b = blockIdx.x;
    const float4* xb = x + (size_t)b * NP;
    const float*  wb = w + (size_t)b * NP;

    float s[45];
#pragma unroll
    for (int k = 0; k < 45; k++) s[k] = 0.f;

    int i = threadIdx.x;
    // software-pipelined quads: prefetch quad at j while accumulating quad at i.
    // Accumulation order per thread: i, i+256, i+512, i+768, then i+1024, ...
    // -- identical chain per s[k] as rounds 2/8.
    {
        float4 p0 = xb[i];
        float  w0 = wb[i];
        float4 p1 = xb[i + 256];
        float  w1 = wb[i + 256];
        float4 p2 = xb[i + 512];
        float  w2 = wb[i + 512];
        float4 p3 = xb[i + 768];
        float  w3 = wb[i + 768];

        int j = i + 1024;
        while (j + 768 < NP) {
            float4 q0 = xb[j];
            float  v0 = wb[j];
            float4 q1 = xb[j + 256];
            float  v1 = wb[j + 256];
            float4 q2 = xb[j + 512];
            float  v2 = wb[j + 512];
            float4 q3 = xb[j + 768];
            float  v3 = wb[j + 768];

            accum_point(p0, w0, s);
            accum_point(p1, w1, s);
            accum_point(p2, w2, s);
            accum_point(p3, w3, s);

            p0 = q0; w0 = v0;
            p1 = q1; w1 = v1;
            p2 = q2; w2 = v2;
            p3 = q3; w3 = v3;
            i = j;
            j += 1024;
        }
        accum_point(p0, w0, s);
        accum_point(p1, w1, s);
        accum_point(p2, w2, s);
        accum_point(p3, w3, s);
        i += 1024;
    }
    for (; i < NP; i += 256) {
        float4 p0 = xb[i];
        float  w0 = wb[i];
        accum_point(p0, w0, s);
    }

    // intra-warp reduction (identical to round 2)
#pragma unroll
    for (int k = 0; k < 45; k++) {
#pragma unroll
        for (int o = 16; o > 0; o >>= 1)
            s[k] += __shfl_xor_sync(0xffffffffu, s[k], o);
    }

    __shared__ float sm[8][45];
    int wid = threadIdx.x >> 5, lane = threadIdx.x & 31;
    if (lane == 0) {
#pragma unroll
        for (int k = 0; k < 45; k++) sm[wid][k] = s[k];
    }
    __syncthreads();
    if (threadIdx.x < 45) {
        float t = 0.f;
#pragma unroll
        for (int q = 0; q < 8; q++) t += sm[q][threadIdx.x];
        g_M[b * 45 + threadIdx.x] = t;
    }
}

// ---------------------------------------------------------------------------
// LAPACK fp32 helpers (identical to round-2 passing kernel)
// ---------------------------------------------------------------------------
#define LEPS    5.9604645e-8f
#define LEPS2   (LEPS * LEPS)
#define LSAFMIN 1.17549435e-38f

__device__ __forceinline__ float slapy2(float x, float y) {
    float xa = fabsf(x), ya = fabsf(y);
    float w = fmaxf(xa, ya), z = fminf(xa, ya);
    if (z == 0.f) return w;
    float t = z / w;
    return w * sqrtf(1.f + t * t);
}

__device__ __forceinline__ void slartg(float f, float g, float& c, float& s, float& r) {
    if (g == 0.f) { c = 1.f; s = 0.f; r = f; }
    else if (f == 0.f) { c = 0.f; s = (g >= 0.f ? 1.f : -1.f); r = fabsf(g); }
    else {
        float d = sqrtf(f * f + g * g);
        c = fabsf(f) / d;
        r = copysignf(d, f);
        s = g / r;
    }
}

__device__ void slaev2(float a, float b, float c,
                       float& rt1, float& rt2, float& cs1, float& sn1) {
    float sm = a + c, df = a - c, adf = fabsf(df);
    float tb = b + b, ab = fabsf(tb);
    float acmx, acmn;
    if (fabsf(a) > fabsf(c)) { acmx = a; acmn = c; } else { acmx = c; acmn = a; }
    float rt;
    if (adf > ab)      { float t = ab / adf; rt = adf * sqrtf(1.f + t * t); }
    else if (adf < ab) { float t = adf / ab; rt = ab * sqrtf(1.f + t * t); }
    else               { rt = ab * sqrtf(2.f); }
    int sgn1;
    if (sm < 0.f) {
        rt1 = 0.5f * (sm - rt); sgn1 = -1;
        rt2 = (acmx / rt1) * acmn - (b / rt1) * b;
    } else if (sm > 0.f) {
        rt1 = 0.5f * (sm + rt); sgn1 = 1;
        rt2 = (acmx / rt1) * acmn - (b / rt1) * b;
    } else {
        rt1 = 0.5f * rt; rt2 = -0.5f * rt; sgn1 = 1;
    }
    float cs; int sgn2;
    if (df >= 0.f) { cs = df + rt; sgn2 = 1; } else { cs = df - rt; sgn2 = -1; }
    float acs = fabsf(cs);
    if (acs > ab) {
        float ct = -tb / cs;
        sn1 = 1.f / sqrtf(1.f + ct * ct);
        cs1 = ct * sn1;
    } else {
        if (ab == 0.f) { cs1 = 1.f; sn1 = 0.f; }
        else {
            float tn = -cs / tb;
            cs1 = 1.f / sqrtf(1.f + tn * tn);
            sn1 = tn * cs1;
        }
    }
    if (sgn1 == sgn2) { float tn = cs1; cs1 = -sn1; sn1 = tn; }
}

// ---------------------------------------------------------------------------
// Kernel 2: per-matrix LAPACK ssyevd replica (ssytd2 + ssteqr + backtransform)
// VERBATIM the round-2 passing version (frozen: any codegen change re-rolls
// the per-batch sign lottery).
// ---------------------------------------------------------------------------
__global__ void eig_kernel(float* __restrict__ out) {
    int b = blockIdx.x;

    float A[9][9];
#pragma unroll
    for (int i = 0; i < 9; i++)
#pragma unroll
        for (int j = i; j < 9; j++) {
            float v = g_M[b * 45 + tidx(i, j)];
            A[i][j] = v; A[j][i] = v;
        }

    float dd[9], e[8], tau[8];

    // ---- ssytd2 (lower) ----
    for (int i = 0; i < 8; i++) {
        float alpha = A[i + 1][i];
        float xn2 = 0.f;
        for (int k = i + 2; k < 9; k++) xn2 += A[k][i] * A[k][i];
        float taui;
        if (xn2 == 0.f) {
            taui = 0.f;
            e[i] = alpha;
        } else {
            float xnorm = sqrtf(xn2);
            float beta = -copysignf(slapy2(alpha, xnorm), alpha);
            taui = (beta - alpha) / beta;
            float invd = 1.f / (alpha - beta);
            for (int k = i + 2; k < 9; k++) A[k][i] *= invd;
            e[i] = beta;
        }
        if (taui != 0.f) {
            float v[9], wv[9];
            v[i + 1] = 1.f;
            for (int k = i + 2; k < 9; k++) v[k] = A[k][i];
            for (int r = i + 1; r < 9; r++) {
                float acc = 0.f;
                for (int c = i + 1; c < 9; c++) acc += A[r][c] * v[c];
                wv[r] = taui * acc;
            }
            float dxv = 0.f;
            for (int r = i + 1; r < 9; r++) dxv += wv[r] * v[r];
            float al2 = -0.5f * taui * dxv;
            for (int r = i + 1; r < 9; r++) wv[r] += al2 * v[r];
            for (int r = i + 1; r < 9; r++)
                for (int c = i + 1; c < 9; c++)
                    A[r][c] -= v[r] * wv[c] + wv[r] * v[c];
        }
        dd[i] = A[i][i];
        tau[i] = taui;
    }
    dd[8] = A[8][8];

    // ---- ssteqr (compz='I') ----
    float Z[9][9];
    for (int r = 0; r < 9; r++)
        for (int c = 0; c < 9; c++) Z[r][c] = (r == c) ? 1.f : 0.f;

    const int NMAXIT = 9 * 30;
    int jtot = 0;
    int l1 = 0;
    while (l1 < 9) {
        if (l1 > 0) e[l1 - 1] = 0.f;
        int m;
        for (m = l1; m < 8; m++) {
            float tst = fabsf(e[m]);
            if (tst == 0.f) break;
            if (tst <= (sqrtf(fabsf(dd[m])) * sqrtf(fabsf(dd[m + 1]))) * LEPS) {
                e[m] = 0.f;
                break;
            }
        }
        int l = l1, lend = m;
        l1 = m + 1;
        if (lend == l) continue;
        if (fabsf(dd[lend]) < fabsf(dd[l])) { int t = l; l = lend; lend = t; }

        if (lend > l) {
            // ---- QL iteration ----
            for (;;) {
                int mm;
                for (mm = l; mm < lend; mm++) {
                    float tst = e[mm] * e[mm];
                    if (tst <= (LEPS2 * fabsf(dd[mm])) * fabsf(dd[mm + 1]) + LSAFMIN) break;
                }
                if (mm < lend) e[mm] = 0.f;
                float p = dd[l];
                if (mm == l) {                       // eigenvalue found
                    dd[l] = p;
                    l++;
                    if (l <= lend) continue;
                    break;
                }
                if (mm == l + 1) {                   // 2x2 block
                    float rt1, rt2, c2, s2;
                    slaev2(dd[l], e[l], dd[l + 1], rt1, rt2, c2, s2);
                    for (int r = 0; r < 9; r++) {
                        float t2 = Z[r][l + 1];
                        Z[r][l + 1] = c2 * t2 - s2 * Z[r][l];
                        Z[r][l]     = s2 * t2 + c2 * Z[r][l];
                    }
                    dd[l] = rt1; dd[l + 1] = rt2; e[l] = 0.f;
                    l += 2;
                    if (l <= lend) continue;
                    break;
                }
                if (jtot >= NMAXIT) break;
                jtot++;
                float g = (dd[l + 1] - p) / (2.f * e[l]);
                float r2 = slapy2(g, 1.f);
                g = dd[mm] - p + e[l] / (g + copysignf(r2, g));
                float s1 = 1.f, c1 = 1.f;
                p = 0.f;
                float cs_[8], sn_[8];
                for (int i = mm - 1; i >= l; i--) {
                    float f = s1 * e[i];
                    float bb = c1 * e[i];
                    slartg(g, f, c1, s1, r2);
                    if (i != mm - 1) e[i + 1] = r2;
                    g = dd[i + 1] - p;
                    r2 = (dd[i] - g) * s1 + 2.f * c1 * bb;
                    p = s1 * r2;
                    dd[i + 1] = g + p;
                    g = c1 * r2 - bb;
                    cs_[i] = c1; sn_[i] = -s1;
                }
                for (int j = mm - 1 - l; j >= 0; j--) {   // slasr 'R','V','B'
                    float cc = cs_[l + j], ss = sn_[l + j];
                    for (int r = 0; r < 9; r++) {
                        float t2 = Z[r][l + j + 1];
                        Z[r][l + j + 1] = cc * t2 - ss * Z[r][l + j];
                        Z[r][l + j]     = ss * t2 + cc * Z[r][l + j];
                    }
                }
                dd[l] = dd[l] - p;
                e[l] = g;
            }
        } else {
            // ---- QR iteration (lend < l) ----
            for (;;) {
                int mm;
                for (mm = l; mm > lend; mm--) {
                    float tst = e[mm - 1] * e[mm - 1];
                    if (tst <= (LEPS2 * fabsf(dd[mm])) * fabsf(dd[mm - 1]) + LSAFMIN) break;
                }
                if (mm > lend) e[mm - 1] = 0.f;
                float p = dd[l];
                if (mm == l) {
                    dd[l] = p;
                    l--;
                    if (l >= lend) continue;
                    break;
                }
                if (mm == l - 1) {
                    float rt1, rt2, c2, s2;
                    slaev2(dd[l - 1], e[l - 1], dd[l], rt1, rt2, c2, s2);
                    for (int r = 0; r < 9; r++) {   // slasr 'F', 2 cols at l-1
                        float t2 = Z[r][l];
                        Z[r][l]     = c2 * t2 - s2 * Z[r][l - 1];
                        Z[r][l - 1] = s2 * t2 + c2 * Z[r][l - 1];
                    }
                    dd[l - 1] = rt1; dd[l] = rt2; e[l - 1] = 0.f;
                    l -= 2;
                    if (l >= lend) continue;
                    break;
                }
                if (jtot >= NMAXIT) break;
                jtot++;
                float g = (dd[l - 1] - p) / (2.f * e[l - 1]);
                float r2 = slapy2(g, 1.f);
                g = dd[mm] - p + e[l - 1] / (g + copysignf(r2, g));
                float s1 = 1.f, c1 = 1.f;
                p = 0.f;
                float cs_[8], sn_[8];
                for (int i = mm; i <= l - 1; i++) {
                    float f = s1 * e[i];
                    float bb = c1 * e[i];
                    slartg(g, f, c1, s1, r2);
                    if (i != mm) e[i - 1] = r2;
                    g = dd[i] - p;
                    r2 = (dd[i + 1] - g) * s1 + 2.f * c1 * bb;
                    p = s1 * r2;
                    dd[i] = g + p;
                    g = c1 * r2 - bb;
                    cs_[i] = c1; sn_[i] = s1;
                }
                for (int j = 0; j <= l - mm - 1; j++) {   // slasr 'R','V','F'
                    float cc = cs_[mm + j], ss = sn_[mm + j];
                    for (int r = 0; r < 9; r++) {
                        float t2 = Z[r][mm + j + 1];
                        Z[r][mm + j + 1] = cc * t2 - ss * Z[r][mm + j];
                        Z[r][mm + j]     = ss * t2 + cc * Z[r][mm + j];
                    }
                }
                dd[l] = dd[l] - p;
                e[l - 1] = g;
            }
        }
    }

    // ---- ssteqr final sort: ascending eigenvalues, swap columns ----
    for (int ii = 1; ii < 9; ii++) {
        int i = ii - 1;
        int k = i;
        float p = dd[i];
        for (int j = ii; j < 9; j++)
            if (dd[j] < p) { k = j; p = dd[j]; }
        if (k != i) {
            dd[k] = dd[i]; dd[i] = p;
            for (int r = 0; r < 9; r++) {
                float t2 = Z[r][i]; Z[r][i] = Z[r][k]; Z[r][k] = t2;
            }
        }
    }

    // ---- back-transform column 0: z <- H(1)...H(8) z ----
    float z[9];
    for (int r = 0; r < 9; r++) z[r] = Z[r][0];
    for (int i = 7; i >= 0; i--) {
        if (tau[i] == 0.f) continue;
        float dot = z[i + 1];
        for (int k = i + 2; k < 9; k++) dot += A[k][i] * z[k];
        float tdot = tau[i] * dot;
        z[i + 1] -= tdot;
        for (int k = i + 2; k < 9; k++) z[k] -= tdot * A[k][i];
    }

    // ---- normalize (reference divides by norm) ----
    float nrm = 0.f;
    for (int k = 0; k < 9; k++) nrm += z[k] * z[k];
    float inv = 1.f / sqrtf(nrm);
    for (int k = 0; k < 9; k++) out[b * 9 + k] = z[k] * inv;
}

extern "C" void kernel_launch(void* const* d_in, const int* in_sizes, int n_in,
                              void* d_out, int out_size) {
    const float4* x = (const float4*)d_in[0];  // x_in  (256,1,20000,4) f32
    const float*  w = (const float*)d_in[1];   // weights (256,20000)   f32
    float* out = (float*)d_out;                // (256,9) f32

    xtx_kernel<<<NB, 256>>>(x, w);
    eig_kernel<<<NB, 1>>>(out);
}

// round 13
// speedup vs baseline: 1.5616x; 1.0864x over previous
#include <cuda_runtime.h>

#define NB 256
#define NP 20000

// scratch: 256 batches x 45 packed upper-triangular entries of XwX
__device__ float g_M[NB * 45];

__device__ __host__ __forceinline__ constexpr int tidx(int i, int j) {
    return 9 * i - i * (i - 1) / 2 + (j - i);
}

// ---------------------------------------------------------------------------
// Kernel 1: per-batch weighted Gram matrix (VERBATIM round-11 passing version;
// software-pipelined loads, bitwise-identical accumulation to round 2).
// ---------------------------------------------------------------------------
__device__ __forceinline__ void accum_point(float4 p, float wt, float* __restrict__ s) {
    float v[9];
    v[0] = p.z * p.x; v[1] = p.z * p.y; v[2] = p.z;
    v[3] = p.w * p.x; v[4] = p.w * p.y; v[5] = p.w;
    v[6] = p.x;       v[7] = p.y;       v[8] = 1.f;
    float wv[9];
#pragma unroll
    for (int k = 0; k < 9; k++) wv[k] = wt * v[k];
    int idx = 0;
#pragma unroll
    for (int i2 = 0; i2 < 9; i2++) {
#pragma unroll
        for (int j = i2; j < 9; j++) {
            s[idx] = fmaf(v[i2], wv[j], s[idx]);
            idx++;
        }
    }
}

__global__ void __launch_bounds__(256) xtx_kernel(const float4* __restrict__ x,
                                                  const float* __restrict__ w) {
    int b = blockIdx.x;
    const float4* xb = x + (size_t)b * NP;
    const float*  wb = w + (size_t)b * NP;

    float s[45];
#pragma unroll
    for (int k = 0; k < 45; k++) s[k] = 0.f;

    int i = threadIdx.x;
    {
        float4 p0 = xb[i];
        float  w0 = wb[i];
        float4 p1 = xb[i + 256];
        float  w1 = wb[i + 256];
        float4 p2 = xb[i + 512];
        float  w2 = wb[i + 512];
        float4 p3 = xb[i + 768];
        float  w3 = wb[i + 768];

        int j = i + 1024;
        while (j + 768 < NP) {
            float4 q0 = xb[j];
            float  v0 = wb[j];
            float4 q1 = xb[j + 256];
            float  v1 = wb[j + 256];
            float4 q2 = xb[j + 512];
            float  v2 = wb[j + 512];
            float4 q3 = xb[j + 768];
            float  v3 = wb[j + 768];

            accum_point(p0, w0, s);
            accum_point(p1, w1, s);
            accum_point(p2, w2, s);
            accum_point(p3, w3, s);

            p0 = q0; w0 = v0;
            p1 = q1; w1 = v1;
            p2 = q2; w2 = v2;
            p3 = q3; w3 = v3;
            i = j;
            j += 1024;
        }
        accum_point(p0, w0, s);
        accum_point(p1, w1, s);
        accum_point(p2, w2, s);
        accum_point(p3, w3, s);
        i += 1024;
    }
    for (; i < NP; i += 256) {
        float4 p0 = xb[i];
        float  w0 = wb[i];
        accum_point(p0, w0, s);
    }

#pragma unroll
    for (int k = 0; k < 45; k++) {
#pragma unroll
        for (int o = 16; o > 0; o >>= 1)
            s[k] += __shfl_xor_sync(0xffffffffu, s[k], o);
    }

    __shared__ float sm[8][45];
    int wid = threadIdx.x >> 5, lane = threadIdx.x & 31;
    if (lane == 0) {
#pragma unroll
        for (int k = 0; k < 45; k++) sm[wid][k] = s[k];
    }
    __syncthreads();
    if (threadIdx.x < 45) {
        float t = 0.f;
#pragma unroll
        for (int q = 0; q < 8; q++) t += sm[q][threadIdx.x];
        g_M[b * 45 + threadIdx.x] = t;
    }
}

// ---------------------------------------------------------------------------
// LAPACK fp32 helpers (identical to round-2 passing kernel)
// ---------------------------------------------------------------------------
#define LEPS    5.9604645e-8f
#define LEPS2   (LEPS * LEPS)
#define LSAFMIN 1.17549435e-38f

__device__ __forceinline__ float slapy2(float x, float y) {
    float xa = fabsf(x), ya = fabsf(y);
    float w = fmaxf(xa, ya), z = fminf(xa, ya);
    if (z == 0.f) return w;
    float t = z / w;
    return w * sqrtf(1.f + t * t);
}

__device__ __forceinline__ void slartg(float f, float g, float& c, float& s, float& r) {
    if (g == 0.f) { c = 1.f; s = 0.f; r = f; }
    else if (f == 0.f) { c = 0.f; s = (g >= 0.f ? 1.f : -1.f); r = fabsf(g); }
    else {
        float d = sqrtf(f * f + g * g);
        c = fabsf(f) / d;
        r = copysignf(d, f);
        s = g / r;
    }
}

__device__ void slaev2(float a, float b, float c,
                       float& rt1, float& rt2, float& cs1, float& sn1) {
    float sm = a + c, df = a - c, adf = fabsf(df);
    float tb = b + b, ab = fabsf(tb);
    float acmx, acmn;
    if (fabsf(a) > fabsf(c)) { acmx = a; acmn = c; } else { acmx = c; acmn = a; }
    float rt;
    if (adf > ab)      { float t = ab / adf; rt = adf * sqrtf(1.f + t * t); }
    else if (adf < ab) { float t = adf / ab; rt = ab * sqrtf(1.f + t * t); }
    else               { rt = ab * sqrtf(2.f); }
    int sgn1;
    if (sm < 0.f) {
        rt1 = 0.5f * (sm - rt); sgn1 = -1;
        rt2 = (acmx / rt1) * acmn - (b / rt1) * b;
    } else if (sm > 0.f) {
        rt1 = 0.5f * (sm + rt); sgn1 = 1;
        rt2 = (acmx / rt1) * acmn - (b / rt1) * b;
    } else {
        rt1 = 0.5f * rt; rt2 = -0.5f * rt; sgn1 = 1;
    }
    float cs; int sgn2;
    if (df >= 0.f) { cs = df + rt; sgn2 = 1; } else { cs = df - rt; sgn2 = -1; }
    float acs = fabsf(cs);
    if (acs > ab) {
        float ct = -tb / cs;
        sn1 = 1.f / sqrtf(1.f + ct * ct);
        cs1 = ct * sn1;
    } else {
        if (ab == 0.f) { cs1 = 1.f; sn1 = 0.f; }
        else {
            float tn = -cs / tb;
            cs1 = 1.f / sqrtf(1.f + tn * tn);
            sn1 = tn * cs1;
        }
    }
    if (sgn1 == sgn2) { float tn = cs1; cs1 = -sn1; sn1 = tn; }
}

// ---------------------------------------------------------------------------
// Warp-parallel Givens on lane-owned Z columns.
// Value-equivalent to round-2's per-row loop:
//   t2 = Z[r][j+1]; Z[r][j+1] = c*t2 - s*Z[r][j]; Z[r][j] = s*t2 + c*Z[r][j];
// Lane k holds Z[0..8][k] in registers zc[9] (static row indices).
// Z feeds no branches, so its rounding/placement cannot change the sign path.
// ---------------------------------------------------------------------------
__device__ __forceinline__ void rot_cols(float* __restrict__ zc, int lane,
                                         int j, float c, float s) {
    bool isj  = (lane == j);
    bool isj1 = (lane == j + 1);
    int src = lane;
    if (isj)  src = j + 1;
    if (isj1) src = j;
#pragma unroll
    for (int r = 0; r < 9; r++) {
        float partner = __shfl_sync(0xffffffffu, zc[r], src);
        float nv = zc[r];
        if (isj1) nv = c * zc[r] - s * partner;   // col j+1 update
        if (isj)  nv = s * partner + c * zc[r];   // col j   update
        zc[r] = nv;
    }
}

// ---------------------------------------------------------------------------
// Kernel 2: LAPACK ssyevd replica, warp-parallel Z.
// 32 lanes per block run the scalar solver redundantly (identical data ->
// uniform branches, identical to round-2 path). Z lives as lane-owned
// register columns; rotations via shuffles. Sort skipped: needed column =
// first-argmin(dd) (round-7-validated equivalence), extracted by shuffle.
// ---------------------------------------------------------------------------
__global__ void __launch_bounds__(32) eig_kernel(float* __restrict__ out) {
    int b = blockIdx.x;
    int lane = threadIdx.x;

    float A[9][9];
#pragma unroll
    for (int i = 0; i < 9; i++)
#pragma unroll
        for (int j = i; j < 9; j++) {
            float v = g_M[b * 45 + tidx(i, j)];
            A[i][j] = v; A[j][i] = v;
        }

    float dd[9], e[8], tau[8];

    // ---- ssytd2 (lower), source-identical to round 2 ----
    for (int i = 0; i < 8; i++) {
        float alpha = A[i + 1][i];
        float xn2 = 0.f;
        for (int k = i + 2; k < 9; k++) xn2 += A[k][i] * A[k][i];
        float taui;
        if (xn2 == 0.f) {
            taui = 0.f;
            e[i] = alpha;
        } else {
            float xnorm = sqrtf(xn2);
            float beta = -copysignf(slapy2(alpha, xnorm), alpha);
            taui = (beta - alpha) / beta;
            float invd = 1.f / (alpha - beta);
            for (int k = i + 2; k < 9; k++) A[k][i] *= invd;
            e[i] = beta;
        }
        if (taui != 0.f) {
            float v[9], wv[9];
            v[i + 1] = 1.f;
            for (int k = i + 2; k < 9; k++) v[k] = A[k][i];
            for (int r = i + 1; r < 9; r++) {
                float acc = 0.f;
                for (int c = i + 1; c < 9; c++) acc += A[r][c] * v[c];
                wv[r] = taui * acc;
            }
            float dxv = 0.f;
            for (int r = i + 1; r < 9; r++) dxv += wv[r] * v[r];
            float al2 = -0.5f * taui * dxv;
            for (int r = i + 1; r < 9; r++) wv[r] += al2 * v[r];
            for (int r = i + 1; r < 9; r++)
                for (int c = i + 1; c < 9; c++)
                    A[r][c] -= v[r] * wv[c] + wv[r] * v[c];
        }
        dd[i] = A[i][i];
        tau[i] = taui;
    }
    dd[8] = A[8][8];

    // ---- Z as lane-owned register columns: Z = I ----
    float zc[9];
#pragma unroll
    for (int r = 0; r < 9; r++) zc[r] = (r == lane) ? 1.f : 0.f;

    // ---- ssteqr (compz='I'), scalar recurrence source-identical ----
    const int NMAXIT = 9 * 30;
    int jtot = 0;
    int l1 = 0;
    while (l1 < 9) {
        if (l1 > 0) e[l1 - 1] = 0.f;
        int m;
        for (m = l1; m < 8; m++) {
            float tst = fabsf(e[m]);
            if (tst == 0.f) break;
            if (tst <= (sqrtf(fabsf(dd[m])) * sqrtf(fabsf(dd[m + 1]))) * LEPS) {
                e[m] = 0.f;
                break;
            }
        }
        int l = l1, lend = m;
        l1 = m + 1;
        if (lend == l) continue;
        if (fabsf(dd[lend]) < fabsf(dd[l])) { int t = l; l = lend; lend = t; }

        if (lend > l) {
            // ---- QL iteration ----
            for (;;) {
                int mm;
                for (mm = l; mm < lend; mm++) {
                    float tst = e[mm] * e[mm];
                    if (tst <= (LEPS2 * fabsf(dd[mm])) * fabsf(dd[mm + 1]) + LSAFMIN) break;
                }
                if (mm < lend) e[mm] = 0.f;
                float p = dd[l];
                if (mm == l) {                       // eigenvalue found
                    dd[l] = p;
                    l++;
                    if (l <= lend) continue;
                    break;
                }
                if (mm == l + 1) {                   // 2x2 block
                    float rt1, rt2, c2, s2;
                    slaev2(dd[l], e[l], dd[l + 1], rt1, rt2, c2, s2);
                    rot_cols(zc, lane, l, c2, s2);
                    dd[l] = rt1; dd[l + 1] = rt2; e[l] = 0.f;
                    l += 2;
                    if (l <= lend) continue;
                    break;
                }
                if (jtot >= NMAXIT) break;
                jtot++;
                float g = (dd[l + 1] - p) / (2.f * e[l]);
                float r2 = slapy2(g, 1.f);
                g = dd[mm] - p + e[l] / (g + copysignf(r2, g));
                float s1 = 1.f, c1 = 1.f;
                p = 0.f;
                float cs_[8], sn_[8];
                for (int i = mm - 1; i >= l; i--) {
                    float f = s1 * e[i];
                    float bb = c1 * e[i];
                    slartg(g, f, c1, s1, r2);
                    if (i != mm - 1) e[i + 1] = r2;
                    g = dd[i + 1] - p;
                    r2 = (dd[i] - g) * s1 + 2.f * c1 * bb;
                    p = s1 * r2;
                    dd[i + 1] = g + p;
                    g = c1 * r2 - bb;
                    cs_[i] = c1; sn_[i] = -s1;
                }
                for (int j = mm - 1 - l; j >= 0; j--) {   // slasr 'R','V','B'
                    rot_cols(zc, lane, l + j, cs_[l + j], sn_[l + j]);
                }
                dd[l] = dd[l] - p;
                e[l] = g;
            }
        } else {
            // ---- QR iteration (lend < l) ----
            for (;;) {
                int mm;
                for (mm = l; mm > lend; mm--) {
                    float tst = e[mm - 1] * e[mm - 1];
                    if (tst <= (LEPS2 * fabsf(dd[mm])) * fabsf(dd[mm - 1]) + LSAFMIN) break;
                }
                if (mm > lend) e[mm - 1] = 0.f;
                float p = dd[l];
                if (mm == l) {
                    dd[l] = p;
                    l--;
                    if (l >= lend) continue;
                    break;
                }
                if (mm == l - 1) {
                    float rt1, rt2, c2, s2;
                    slaev2(dd[l - 1], e[l - 1], dd[l], rt1, rt2, c2, s2);
                    rot_cols(zc, lane, l - 1, c2, s2);
                    dd[l - 1] = rt1; dd[l] = rt2; e[l - 1] = 0.f;
                    l -= 2;
                    if (l >= lend) continue;
                    break;
                }
                if (jtot >= NMAXIT) break;
                jtot++;
                float g = (dd[l - 1] - p) / (2.f * e[l - 1]);
                float r2 = slapy2(g, 1.f);
                g = dd[mm] - p + e[l - 1] / (g + copysignf(r2, g));
                float s1 = 1.f, c1 = 1.f;
                p = 0.f;
                float cs_[8], sn_[8];
                for (int i = mm; i <= l - 1; i++) {
                    float f = s1 * e[i];
                    float bb = c1 * e[i];
                    slartg(g, f, c1, s1, r2);
                    if (i != mm) e[i - 1] = r2;
                    g = dd[i] - p;
                    r2 = (dd[i + 1] - g) * s1 + 2.f * c1 * bb;
                    p = s1 * r2;
                    dd[i] = g + p;
                    g = c1 * r2 - bb;
                    cs_[i] = c1; sn_[i] = s1;
                }
                for (int j = 0; j <= l - mm - 1; j++) {   // slasr 'R','V','F'
                    rot_cols(zc, lane, mm + j, cs_[mm + j], sn_[mm + j]);
                }
                dd[l] = dd[l] - p;
                e[l - 1] = g;
            }
        }
    }

    // ---- column the sort would put at index 0 = first strict argmin of dd ----
    int kmin = 0;
    float p0 = dd[0];
    for (int j = 1; j < 9; j++)
        if (dd[j] < p0) { p0 = dd[j]; kmin = j; }

    // ---- extract column kmin (broadcast lane kmin's registers) ----
    float z[9];
#pragma unroll
    for (int r = 0; r < 9; r++) z[r] = __shfl_sync(0xffffffffu, zc[r], kmin);

    // ---- back-transform: z <- H(1)...H(8) z (source-identical) ----
    for (int i = 7; i >= 0; i--) {
        if (tau[i] == 0.f) continue;
        float dot = z[i + 1];
        for (int k = i + 2; k < 9; k++) dot += A[k][i] * z[k];
        float tdot = tau[i] * dot;
        z[i + 1] -= tdot;
        for (int k = i + 2; k < 9; k++) z[k] -= tdot * A[k][i];
    }

    // ---- normalize ----
    float nrm = 0.f;
    for (int k = 0; k < 9; k++) nrm += z[k] * z[k];
    float inv = 1.f / sqrtf(nrm);
    if (lane == 0) {
        for (int k = 0; k < 9; k++) out[b * 9 + k] = z[k] * inv;
    }
}

extern "C" void kernel_launch(void* const* d_in, const int* in_sizes, int n_in,
                              void* d_out, int out_size) {
    const float4* x = (const float4*)d_in[0];  // x_in  (256,1,20000,4) f32
    const float*  w = (const float*)d_in[1];   // weights (256,20000)   f32
    float* out = (float*)d_out;                // (256,9) f32

    xtx_kernel<<<NB, 256>>>(x, w);
    eig_kernel<<<NB, 32>>>(out);
}

// round 14
// speedup vs baseline: 1.9486x; 1.2478x over previous
#include <cuda_runtime.h>

#define NB 256
#define NP 20000

__device__ float g_M[NB * 45];

__device__ __host__ __forceinline__ constexpr int tidx(int i, int j) {
    return 9 * i - i * (i - 1) / 2 + (j - i);
}

// ---------------------------------------------------------------------------
// Kernel 1: per-batch weighted Gram matrix (VERBATIM round-11/13 passing
// version; software-pipelined loads, bitwise-identical accumulation).
// ---------------------------------------------------------------------------
__device__ __forceinline__ void accum_point(float4 p, float wt, float* __restrict__ s) {
    float v[9];
    v[0] = p.z * p.x; v[1] = p.z * p.y; v[2] = p.z;
    v[3] = p.w * p.x; v[4] = p.w * p.y; v[5] = p.w;
    v[6] = p.x;       v[7] = p.y;       v[8] = 1.f;
    float wv[9];
#pragma unroll
    for (int k = 0; k < 9; k++) wv[k] = wt * v[k];
    int idx = 0;
#pragma unroll
    for (int i2 = 0; i2 < 9; i2++) {
#pragma unroll
        for (int j = i2; j < 9; j++) {
            s[idx] = fmaf(v[i2], wv[j], s[idx]);
            idx++;
        }
    }
}

__global__ void __launch_bounds__(256) xtx_kernel(const float4* __restrict__ x,
                                                  const float* __restrict__ w) {
    int b = blockIdx.x;
    const float4* xb = x + (size_t)b * NP;
    const float*  wb = w + (size_t)b * NP;

    float s[45];
#pragma unroll
    for (int k = 0; k < 45; k++) s[k] = 0.f;

    int i = threadIdx.x;
    {
        float4 p0 = xb[i];
        float  w0 = wb[i];
        float4 p1 = xb[i + 256];
        float  w1 = wb[i + 256];
        float4 p2 = xb[i + 512];
        float  w2 = wb[i + 512];
        float4 p3 = xb[i + 768];
        float  w3 = wb[i + 768];

        int j = i + 1024;
        while (j + 768 < NP) {
            float4 q0 = xb[j];
            float  v0 = wb[j];
            float4 q1 = xb[j + 256];
            float  v1 = wb[j + 256];
            float4 q2 = xb[j + 512];
            float  v2 = wb[j + 512];
            float4 q3 = xb[j + 768];
            float  v3 = wb[j + 768];

            accum_point(p0, w0, s);
            accum_point(p1, w1, s);
            accum_point(p2, w2, s);
            accum_point(p3, w3, s);

            p0 = q0; w0 = v0;
            p1 = q1; w1 = v1;
            p2 = q2; w2 = v2;
            p3 = q3; w3 = v3;
            i = j;
            j += 1024;
        }
        accum_point(p0, w0, s);
        accum_point(p1, w1, s);
        accum_point(p2, w2, s);
        accum_point(p3, w3, s);
        i += 1024;
    }
    for (; i < NP; i += 256) {
        float4 p0 = xb[i];
        float  w0 = wb[i];
        accum_point(p0, w0, s);
    }

#pragma unroll
    for (int k = 0; k < 45; k++) {
#pragma unroll
        for (int o = 16; o > 0; o >>= 1)
            s[k] += __shfl_xor_sync(0xffffffffu, s[k], o);
    }

    __shared__ float sm[8][45];
    int wid = threadIdx.x >> 5, lane = threadIdx.x & 31;
    if (lane == 0) {
#pragma unroll
        for (int k = 0; k < 45; k++) sm[wid][k] = s[k];
    }
    __syncthreads();
    if (threadIdx.x < 45) {
        float t = 0.f;
#pragma unroll
        for (int q = 0; q < 8; q++) t += sm[q][threadIdx.x];
        g_M[b * 45 + threadIdx.x] = t;
    }
}

// ---------------------------------------------------------------------------
// LAPACK fp32 helpers (identical expressions to round-2 passing kernel)
// ---------------------------------------------------------------------------
#define LEPS    5.9604645e-8f
#define LEPS2   (LEPS * LEPS)
#define LSAFMIN 1.17549435e-38f

__device__ __forceinline__ float slapy2(float x, float y) {
    float xa = fabsf(x), ya = fabsf(y);
    float w = fmaxf(xa, ya), z = fminf(xa, ya);
    if (z == 0.f) return w;
    float t = z / w;
    return w * sqrtf(1.f + t * t);
}

__device__ __forceinline__ void slartg(float f, float g, float& c, float& s, float& r) {
    if (g == 0.f) { c = 1.f; s = 0.f; r = f; }
    else if (f == 0.f) { c = 0.f; s = (g >= 0.f ? 1.f : -1.f); r = fabsf(g); }
    else {
        float d = sqrtf(f * f + g * g);
        c = fabsf(f) / d;
        r = copysignf(d, f);
        s = g / r;
    }
}

__device__ __forceinline__ void slaev2(float a, float b, float c,
                       float& rt1, float& rt2, float& cs1, float& sn1) {
    float sm = a + c, df = a - c, adf = fabsf(df);
    float tb = b + b, ab = fabsf(tb);
    float acmx, acmn;
    if (fabsf(a) > fabsf(c)) { acmx = a; acmn = c; } else { acmx = c; acmn = a; }
    float rt;
    if (adf > ab)      { float t = ab / adf; rt = adf * sqrtf(1.f + t * t); }
    else if (adf < ab) { float t = adf / ab; rt = ab * sqrtf(1.f + t * t); }
    else               { rt = ab * sqrtf(2.f); }
    int sgn1;
    if (sm < 0.f) {
        rt1 = 0.5f * (sm - rt); sgn1 = -1;
        rt2 = (acmx / rt1) * acmn - (b / rt1) * b;
    } else if (sm > 0.f) {
        rt1 = 0.5f * (sm + rt); sgn1 = 1;
        rt2 = (acmx / rt1) * acmn - (b / rt1) * b;
    } else {
        rt1 = 0.5f * rt; rt2 = -0.5f * rt; sgn1 = 1;
    }
    float cs; int sgn2;
    if (df >= 0.f) { cs = df + rt; sgn2 = 1; } else { cs = df - rt; sgn2 = -1; }
    float acs = fabsf(cs);
    if (acs > ab) {
        float ct = -tb / cs;
        sn1 = 1.f / sqrtf(1.f + ct * ct);
        cs1 = ct * sn1;
    } else {
        if (ab == 0.f) { cs1 = 1.f; sn1 = 0.f; }
        else {
            float tn = -cs / tb;
            cs1 = 1.f / sqrtf(1.f + tn * tn);
            sn1 = tn * cs1;
        }
    }
    if (sgn1 == sgn2) { float tn = cs1; cs1 = -sn1; sn1 = tn; }
}

// 9-way predicated select / update (exact moves; no arithmetic)
__device__ __forceinline__ float sel9(const float* a, int k) {
    float r = a[0];
#pragma unroll
    for (int t = 1; t < 9; t++) r = (t == k) ? a[t] : r;
    return r;
}
__device__ __forceinline__ void upd9(float* a, int k, float v) {
#pragma unroll
    for (int t = 0; t < 9; t++) a[t] = (t == k) ? v : a[t];
}

// ---------------------------------------------------------------------------
// Warp-parallel Givens on lane-owned Z columns (round-13 passing version).
// ---------------------------------------------------------------------------
__device__ __forceinline__ void rot_cols(float* __restrict__ zc, int lane,
                                         int j, float c, float s) {
    bool isj  = (lane == j);
    bool isj1 = (lane == j + 1);
    int src = lane;
    if (isj)  src = j + 1;
    if (isj1) src = j;
#pragma unroll
    for (int r = 0; r < 9; r++) {
        float partner = __shfl_sync(0xffffffffu, zc[r], src);
        float nv = zc[r];
        if (isj1) nv = c * zc[r] - s * partner;
        if (isj)  nv = s * partner + c * zc[r];
        zc[r] = nv;
    }
}

// ---------------------------------------------------------------------------
// Kernel 2: LAPACK ssyevd replica, register-resident scalar state.
// Every statement textually identical to the round-2/13 passing solver;
// loops statically unrolled with uniform runtime predicates so dd/e/A/tau
// stay in registers. Scans evaluate all slots and commit the first hit
// (same selected index as the serial break). Rotations fused into the
// recurrence (generation order == application order in both variants).
// ---------------------------------------------------------------------------
__global__ void __launch_bounds__(32) eig_kernel(float* __restrict__ out) {
    int b = blockIdx.x;
    int lane = threadIdx.x;

    float A[9][9];
#pragma unroll
    for (int i = 0; i < 9; i++)
#pragma unroll
        for (int j = i; j < 9; j++) {
            float v = g_M[b * 45 + tidx(i, j)];
            A[i][j] = v; A[j][i] = v;
        }

    float dd[9], e[9], tau[8];

    // ---- ssytd2 (lower), statements identical, fully unrolled ----
#pragma unroll
    for (int i = 0; i < 8; i++) {
        float alpha = A[i + 1][i];
        float xn2 = 0.f;
#pragma unroll
        for (int k = i + 2; k < 9; k++) xn2 += A[k][i] * A[k][i];
        float taui;
        if (xn2 == 0.f) {
            taui = 0.f;
            e[i] = alpha;
        } else {
            float xnorm = sqrtf(xn2);
            float beta = -copysignf(slapy2(alpha, xnorm), alpha);
            taui = (beta - alpha) / beta;
            float invd = 1.f / (alpha - beta);
#pragma unroll
            for (int k = i + 2; k < 9; k++) A[k][i] *= invd;
            e[i] = beta;
        }
        if (taui != 0.f) {
            float v[9], wv[9];
            v[i + 1] = 1.f;
#pragma unroll
            for (int k = i + 2; k < 9; k++) v[k] = A[k][i];
#pragma unroll
            for (int r = i + 1; r < 9; r++) {
                float acc = 0.f;
#pragma unroll
                for (int c = i + 1; c < 9; c++) acc += A[r][c] * v[c];
                wv[r] = taui * acc;
            }
            float dxv = 0.f;
#pragma unroll
            for (int r = i + 1; r < 9; r++) dxv += wv[r] * v[r];
            float al2 = -0.5f * taui * dxv;
#pragma unroll
            for (int r = i + 1; r < 9; r++) wv[r] += al2 * v[r];
#pragma unroll
            for (int r = i + 1; r < 9; r++)
#pragma unroll
                for (int c = i + 1; c < 9; c++)
                    A[r][c] -= v[r] * wv[c] + wv[r] * v[c];
        }
        dd[i] = A[i][i];
        tau[i] = taui;
    }
    dd[8] = A[8][8];

    // ---- Z as lane-owned register columns ----
    float zc[9];
#pragma unroll
    for (int r = 0; r < 9; r++) zc[r] = (r == lane) ? 1.f : 0.f;

    // ---- ssteqr (compz='I') ----
    const int NMAXIT = 9 * 30;
    int jtot = 0;
    int l1 = 0;
    while (l1 < 9) {
        if (l1 > 0) upd9(e, l1 - 1, 0.f);
        int m = 8;
        {
            bool found = false;
#pragma unroll
            for (int t = 0; t < 8; t++) {
                if (!found && t >= l1) {
                    float tst = fabsf(e[t]);
                    if (tst == 0.f) { m = t; found = true; }
                    else if (tst <= (sqrtf(fabsf(dd[t])) * sqrtf(fabsf(dd[t + 1]))) * LEPS) {
                        e[t] = 0.f;
                        m = t; found = true;
                    }
                }
            }
        }
        int l = l1, lend = m;
        l1 = m + 1;
        if (lend == l) continue;
        if (fabsf(sel9(dd, lend)) < fabsf(sel9(dd, l))) { int t = l; l = lend; lend = t; }

        if (lend > l) {
            // ---- QL iteration ----
            for (;;) {
                int mm = lend;
                {
                    bool found = false;
#pragma unroll
                    for (int t = 0; t < 8; t++) {
                        if (!found && t >= l && t < lend) {
                            float tst = e[t] * e[t];
                            if (tst <= (LEPS2 * fabsf(dd[t])) * fabsf(dd[t + 1]) + LSAFMIN) {
                                mm = t; found = true;
                                e[t] = 0.f;
                            }
                        }
                    }
                }
                float p = sel9(dd, l);
                if (mm == l) {
                    l++;
                    if (l <= lend) continue;
                    break;
                }
                if (mm == l + 1) {
                    float rt1, rt2, c2, s2;
                    slaev2(sel9(dd, l), sel9(e, l), sel9(dd, l + 1), rt1, rt2, c2, s2);
                    rot_cols(zc, lane, l, c2, s2);
                    upd9(dd, l, rt1); upd9(dd, l + 1, rt2); upd9(e, l, 0.f);
                    l += 2;
                    if (l <= lend) continue;
                    break;
                }
                if (jtot >= NMAXIT) break;
                jtot++;
                float g = (sel9(dd, l + 1) - p) / (2.f * sel9(e, l));
                float r2 = slapy2(g, 1.f);
                g = sel9(dd, mm) - p + sel9(e, l) / (g + copysignf(r2, g));
                float s1 = 1.f, c1 = 1.f;
                p = 0.f;
#pragma unroll
                for (int i = 7; i >= 0; i--) {
                    if (i <= mm - 1 && i >= l) {
                        float f = s1 * e[i];
                        float bb = c1 * e[i];
                        slartg(g, f, c1, s1, r2);
                        if (i != mm - 1) e[i + 1] = r2;
                        g = dd[i + 1] - p;
                        r2 = (dd[i] - g) * s1 + 2.f * c1 * bb;
                        p = s1 * r2;
                        dd[i + 1] = g + p;
                        g = c1 * r2 - bb;
                        rot_cols(zc, lane, i, c1, -s1);
                    }
                }
                upd9(dd, l, sel9(dd, l) - p);
                upd9(e, l, g);
            }
        } else {
            // ---- QR iteration (lend < l) ----
            for (;;) {
                int mm = lend;
                {
                    bool found = false;
#pragma unroll
                    for (int t = 8; t >= 1; t--) {
                        if (!found && t <= l && t > lend) {
                            float tst = e[t - 1] * e[t - 1];
                            if (tst <= (LEPS2 * fabsf(dd[t])) * fabsf(dd[t - 1]) + LSAFMIN) {
                                mm = t; found = true;
                                e[t - 1] = 0.f;
                            }
                        }
                    }
                }
                float p = sel9(dd, l);
                if (mm == l) {
                    l--;
                    if (l >= lend) continue;
                    break;
                }
                if (mm == l - 1) {
                    float rt1, rt2, c2, s2;
                    slaev2(sel9(dd, l - 1), sel9(e, l - 1), sel9(dd, l), rt1, rt2, c2, s2);
                    rot_cols(zc, lane, l - 1, c2, s2);
                    upd9(dd, l - 1, rt1); upd9(dd, l, rt2); upd9(e, l - 1, 0.f);
                    l -= 2;
                    if (l >= lend) continue;
                    break;
                }
                if (jtot >= NMAXIT) break;
                jtot++;
                float g = (sel9(dd, l - 1) - p) / (2.f * sel9(e, l - 1));
                float r2 = slapy2(g, 1.f);
                g = sel9(dd, mm) - p + sel9(e, l - 1) / (g + copysignf(r2, g));
                float s1 = 1.f, c1 = 1.f;
                p = 0.f;
#pragma unroll
                for (int i = 0; i < 8; i++) {
                    if (i >= mm && i <= l - 1) {
                        float f = s1 * e[i];
                        float bb = c1 * e[i];
                        slartg(g, f, c1, s1, r2);
                        if (i > 0 && i != mm) e[i - 1] = r2;
                        g = dd[i] - p;
                        r2 = (dd[i + 1] - g) * s1 + 2.f * c1 * bb;
                        p = s1 * r2;
                        dd[i] = g + p;
                        g = c1 * r2 - bb;
                        rot_cols(zc, lane, i, c1, s1);
                    }
                }
                upd9(dd, l, sel9(dd, l) - p);
                upd9(e, l - 1, g);
            }
        }
    }

    // ---- first strict argmin of dd (== sort's column 0) ----
    int kmin = 0;
    float p0 = dd[0];
#pragma unroll
    for (int j = 1; j < 9; j++)
        if (dd[j] < p0) { p0 = dd[j]; kmin = j; }

    // ---- extract column kmin ----
    float z[9];
#pragma unroll
    for (int r = 0; r < 9; r++) z[r] = __shfl_sync(0xffffffffu, zc[r], kmin);

    // ---- back-transform: z <- H(1)...H(8) z ----
#pragma unroll
    for (int i = 7; i >= 0; i--) {
        if (tau[i] != 0.f) {
            float dot = z[i + 1];
#pragma unroll
            for (int k = i + 2; k < 9; k++) dot += A[k][i] * z[k];
            float tdot = tau[i] * dot;
            z[i + 1] -= tdot;
#pragma unroll
            for (int k = i + 2; k < 9; k++) z[k] -= tdot * A[k][i];
        }
    }

    // ---- normalize ----
    float nrm = 0.f;
#pragma unroll
    for (int k = 0; k < 9; k++) nrm += z[k] * z[k];
    float inv = 1.f / sqrtf(nrm);
    if (lane == 0) {
#pragma unroll
        for (int k = 0; k < 9; k++) out[b * 9 + k] = z[k] * inv;
    }
}

extern "C" void kernel_launch(void* const* d_in, const int* in_sizes, int n_in,
                              void* d_out, int out_size) {
    const float4* x = (const float4*)d_in[0];  // x_in  (256,1,20000,4) f32
    const float*  w = (const float*)d_in[1];   // weights (256,20000)   f32
    float* out = (float*)d_out;                // (256,9) f32

    xtx_kernel<<<NB, 256>>>(x, w);
    eig_kernel<<<NB, 32>>>(out);
}